// round 5
// baseline (speedup 1.0000x reference)
#include <cuda_runtime.h>

// DPLoss: masked per-row MSE of (pred - log(alignment)), normalized by row
// length, then mean over batch.
//
// Inputs (metadata order):
//   d_in[0] = pred            float32 [B, T]
//   d_in[1] = alignment       float32 [B, T]
//   d_in[2] = token_lengths   int32   [B]
// Output: scalar float32.
//
// Design (R2):
//  - 2D grid (row, chunk): each 128-thread block owns a 256-float4 chunk of
//    one row; blocks entirely past the row's valid length exit immediately.
//    Uniform block cost -> no long-row tail waves.
//  - Each thread loads 2 float4 pairs (4 LDG.128) up front -> MLP=4.
//  - Block partials scattered via atomicAdd across 64 scratch slots (kills
//    the single-address L2 atomic serialization), tiny 3rd kernel folds the
//    slots into the scalar output.

#define CHUNK_VECS 256          // float4 vectors per block (= 1024 elements)
#define BLOCK_THREADS 128
#define NSLOTS 64

__device__ float g_slots[NSLOTS];

__global__ void dploss_zero_slots() {
    g_slots[threadIdx.x] = 0.0f;
}

__global__ __launch_bounds__(BLOCK_THREADS) void dploss_main(
    const float* __restrict__ pred,
    const float* __restrict__ alignment,
    const int*   __restrict__ lens,
    int T, float inv_B)
{
    const int row = blockIdx.x;
    const int len = lens[row];
    const int nvec = (len + 3) >> 2;
    const int chunk0 = blockIdx.y * CHUNK_VECS;

    if (chunk0 >= nvec) return;          // whole chunk beyond valid length

    const float4* __restrict__ p4 =
        reinterpret_cast<const float4*>(pred + (size_t)row * T);
    const float4* __restrict__ a4 =
        reinterpret_cast<const float4*>(alignment + (size_t)row * T);

    const int v0 = chunk0 + threadIdx.x;
    const int v1 = v0 + BLOCK_THREADS;
    const bool m0 = v0 < nvec;
    const bool m1 = v1 < nvec;

    // Front-load all global reads (up to 4 LDG.128 in flight per thread).
    float4 p0, a0, p1, a1;
    if (m0) { p0 = p4[v0]; a0 = a4[v0]; }
    if (m1) { p1 = p4[v1]; a1 = a4[v1]; }

    float acc = 0.0f;

    if (m0) {
        const int base = v0 << 2;
        if (base + 4 <= len) {
            float d0 = p0.x - __logf(a0.x);
            float d1 = p0.y - __logf(a0.y);
            float d2 = p0.z - __logf(a0.z);
            float d3 = p0.w - __logf(a0.w);
            acc = fmaf(d0, d0, acc);
            acc = fmaf(d1, d1, acc);
            acc = fmaf(d2, d2, acc);
            acc = fmaf(d3, d3, acc);
        } else {
            if (base + 0 < len) { float d = p0.x - __logf(a0.x); acc = fmaf(d, d, acc); }
            if (base + 1 < len) { float d = p0.y - __logf(a0.y); acc = fmaf(d, d, acc); }
            if (base + 2 < len) { float d = p0.z - __logf(a0.z); acc = fmaf(d, d, acc); }
            if (base + 3 < len) { float d = p0.w - __logf(a0.w); acc = fmaf(d, d, acc); }
        }
    }
    if (m1) {
        const int base = v1 << 2;
        if (base + 4 <= len) {
            float d0 = p1.x - __logf(a1.x);
            float d1 = p1.y - __logf(a1.y);
            float d2 = p1.z - __logf(a1.z);
            float d3 = p1.w - __logf(a1.w);
            acc = fmaf(d0, d0, acc);
            acc = fmaf(d1, d1, acc);
            acc = fmaf(d2, d2, acc);
            acc = fmaf(d3, d3, acc);
        } else {
            if (base + 0 < len) { float d = p1.x - __logf(a1.x); acc = fmaf(d, d, acc); }
            if (base + 1 < len) { float d = p1.y - __logf(a1.y); acc = fmaf(d, d, acc); }
            if (base + 2 < len) { float d = p1.z - __logf(a1.z); acc = fmaf(d, d, acc); }
            if (base + 3 < len) { float d = p1.w - __logf(a1.w); acc = fmaf(d, d, acc); }
        }
    }

    // ---- block reduction: warp shuffle, then smem across 4 warps ----
    #pragma unroll
    for (int off = 16; off > 0; off >>= 1)
        acc += __shfl_xor_sync(0xFFFFFFFFu, acc, off);

    __shared__ float warp_sums[4];
    const int wid = threadIdx.x >> 5;
    const int lid = threadIdx.x & 31;
    if (lid == 0) warp_sums[wid] = acc;
    __syncthreads();

    if (threadIdx.x == 0) {
        float s = warp_sums[0] + warp_sums[1] + warp_sums[2] + warp_sums[3];
        const int slot = (blockIdx.x * gridDim.y + blockIdx.y) & (NSLOTS - 1);
        atomicAdd(&g_slots[slot], s * inv_B / (float)len);
    }
}

__global__ void dploss_final(float* __restrict__ out) {
    // 64 threads = 2 warps; reduce 64 slots to a scalar.
    float v = g_slots[threadIdx.x];
    #pragma unroll
    for (int off = 16; off > 0; off >>= 1)
        v += __shfl_xor_sync(0xFFFFFFFFu, v, off);

    __shared__ float ws[2];
    if ((threadIdx.x & 31) == 0) ws[threadIdx.x >> 5] = v;
    __syncthreads();
    if (threadIdx.x == 0) out[0] = ws[0] + ws[1];
}

extern "C" void kernel_launch(void* const* d_in, const int* in_sizes, int n_in,
                              void* d_out, int out_size)
{
    const float* pred      = (const float*)d_in[0];
    const float* alignment = (const float*)d_in[1];
    const int*   lens      = (const int*)d_in[2];
    float*       out       = (float*)d_out;

    const int B = in_sizes[2];
    const int T = in_sizes[0] / B;

    const int nvec_total = T >> 2;                       // float4 per row
    const int chunks = (nvec_total + CHUNK_VECS - 1) / CHUNK_VECS;

    dploss_zero_slots<<<1, NSLOTS>>>();
    dim3 grid(B, chunks);
    dploss_main<<<grid, BLOCK_THREADS>>>(pred, alignment, lens, T,
                                         1.0f / (float)B);
    dploss_final<<<1, NSLOTS>>>(out);
}